// round 7
// baseline (speedup 1.0000x reference)
#include <cuda_runtime.h>
#include <cstdint>

#define D 128
#define P 8
#define NMAX 100352     // padded capacity (multiple of 256)
#define LMAX 3
#define BS_STRIDE 72    // Bs stride: frag bank = (8t + 8j + g) % 32, all distinct

// Scratch (device globals — no allocation allowed)
__device__ float g_axT[(size_t)NMAX * D];   // SpMM output, COLUMN-major: [k][row], stride NP
__device__ float g_hA[(size_t)NMAX * D];
__device__ float g_hB[(size_t)NMAX * D];
__device__ int   g_row_ptr[NMAX + 1];
__device__ float g_wwT[LMAX * D * D];       // [l][k][o]

// ---------------------------------------------------------------------------
__global__ void build_row_ptr_k(const int* __restrict__ edge_row, int E, int N) {
    int r = blockIdx.x * blockDim.x + threadIdx.x;
    if (r > N) return;
    int lo = 0, hi = E;
    while (lo < hi) {
        int mid = (lo + hi) >> 1;
        if (edge_row[mid] < r) lo = mid + 1; else hi = mid;
    }
    g_row_ptr[r] = lo;
}

// ---------------------------------------------------------------------------
__global__ void build_weights_k(const float* __restrict__ sp, const float* __restrict__ lw) {
    int l = blockIdx.x >> 7;
    int i = blockIdx.x & 127;
    int o = threadIdx.x;

    float w[P];
    float m = -1e30f;
#pragma unroll
    for (int p = 0; p < P; p++) { w[p] = lw[l * P + p]; m = fmaxf(m, w[p]); }
    float s = 0.f;
#pragma unroll
    for (int p = 0; p < P; p++) { w[p] = expf(w[p] - m); s += w[p]; }
    float inv = 1.f / s;

    const float* base = sp + (((size_t)l * D + o) * D + i) * P;
    float acc = 0.f;
#pragma unroll
    for (int p = 0; p < P; p++) acc = fmaf(base[p], w[p] * inv, acc);
    g_wwT[((size_t)l * D + i) * D + o] = acc;
}

// ---------------------------------------------------------------------------
// SpMM with transposed output: one warp per row, 2-edge unroll; block stages
// its 8 rows in smem then writes axT[k][row] with full 32B sectors.
// ---------------------------------------------------------------------------
__global__ void spmm_t_k(const int* __restrict__ col, const float* __restrict__ val,
                         const float* __restrict__ h, int N, int NP) {
    __shared__ float sh[8][128];
    const int warp = threadIdx.x >> 5;
    const int lane = threadIdx.x & 31;
    const int r = blockIdx.x * 8 + warp;

    float4 acc0 = make_float4(0.f, 0.f, 0.f, 0.f);
    float4 acc1 = make_float4(0.f, 0.f, 0.f, 0.f);
    if (r < N) {
        int s = g_row_ptr[r];
        int e = g_row_ptr[r + 1];
        int k = s;
        for (; k + 1 < e; k += 2) {
            int   c0 = __ldg(col + k);
            int   c1 = __ldg(col + k + 1);
            float v0 = __ldg(val + k);
            float v1 = __ldg(val + k + 1);
            float4 h0 = __ldg(((const float4*)(h + (size_t)c0 * D)) + lane);
            float4 h1 = __ldg(((const float4*)(h + (size_t)c1 * D)) + lane);
            acc0.x = fmaf(v0, h0.x, acc0.x); acc0.y = fmaf(v0, h0.y, acc0.y);
            acc0.z = fmaf(v0, h0.z, acc0.z); acc0.w = fmaf(v0, h0.w, acc0.w);
            acc1.x = fmaf(v1, h1.x, acc1.x); acc1.y = fmaf(v1, h1.y, acc1.y);
            acc1.z = fmaf(v1, h1.z, acc1.z); acc1.w = fmaf(v1, h1.w, acc1.w);
        }
        if (k < e) {
            int   c0 = __ldg(col + k);
            float v0 = __ldg(val + k);
            float4 h0 = __ldg(((const float4*)(h + (size_t)c0 * D)) + lane);
            acc0.x = fmaf(v0, h0.x, acc0.x); acc0.y = fmaf(v0, h0.y, acc0.y);
            acc0.z = fmaf(v0, h0.z, acc0.z); acc0.w = fmaf(v0, h0.w, acc0.w);
        }
    }
    acc0.x += acc1.x; acc0.y += acc1.y; acc0.z += acc1.z; acc0.w += acc1.w;
    *(float4*)&sh[warp][lane * 4] = acc0;
    __syncthreads();

    // transpose-out: thread t<128 owns column k=t; writes 8 row-values
    // (two adjacent float4s = one full 32B sector per k).
    const int t = threadIdx.x;
    if (t < 128) {
        const int r0 = blockIdx.x * 8;
        float4 v0 = make_float4(sh[0][t], sh[1][t], sh[2][t], sh[3][t]);
        float4 v1 = make_float4(sh[4][t], sh[5][t], sh[6][t], sh[7][t]);
        float* dst = g_axT + (size_t)t * NP + r0;
        *(float4*)(dst)     = v0;
        *(float4*)(dst + 4) = v1;
    }
}

// ---------------------------------------------------------------------------
__device__ __forceinline__ void mma_tf32(float (&d)[4],
                                         uint32_t a0, uint32_t a1, uint32_t a2, uint32_t a3,
                                         uint32_t b0, uint32_t b1) {
    asm volatile(
        "mma.sync.aligned.m16n8k8.row.col.f32.tf32.tf32.f32 "
        "{%0,%1,%2,%3},{%4,%5,%6,%7},{%8,%9},{%0,%1,%2,%3};"
        : "+f"(d[0]), "+f"(d[1]), "+f"(d[2]), "+f"(d[3])
        : "r"(a0), "r"(a1), "r"(a2), "r"(a3), "r"(b0), "r"(b1));
}

__device__ __forceinline__ void split_tf32(float v, uint32_t& hi, uint32_t& lo) {
    uint32_t h = __float_as_uint(v) & 0xffffe000u;
    hi = h;
    lo = __float_as_uint(v - __uint_as_float(h));
}

// ---------------------------------------------------------------------------
// Tensor-core GEMM (3xTF32): A is COLUMN-major (axT, stride NP) so fragment
// LDGs are sector-perfect. Block = 256 rows x 64 cols, warp = 32 rows x 64.
// B pre-split hi/lo in smem; 2 blocks/SM.
// ---------------------------------------------------------------------------
template <bool RELU>
__global__ __launch_bounds__(256, 2) void gemm_tc(const float* __restrict__ AT,
                                                  const float* __restrict__ B,
                                                  float* __restrict__ C, int N, int NP) {
    extern __shared__ float smem[];
    float* BsH = smem;                    // [128][BS_STRIDE]
    float* BsL = smem + 128 * BS_STRIDE;  // [128][BS_STRIDE]

    const int tid     = threadIdx.x;
    const int col_off = (blockIdx.x & 1) << 6;   // 0 or 64

    // stage B slice (128 x 64), split hi/lo once
#pragma unroll
    for (int i = tid; i < 128 * 16; i += 256) {
        int row = i >> 4;
        int c4  = (i & 15) << 2;
        float4 v = __ldg((const float4*)(B + row * 128 + col_off + c4));
        float* dh = &BsH[row * BS_STRIDE + c4];
        float* dl = &BsL[row * BS_STRIDE + c4];
        uint32_t h0, l0, h1, l1, h2, l2, h3, l3;
        split_tf32(v.x, h0, l0); split_tf32(v.y, h1, l1);
        split_tf32(v.z, h2, l2); split_tf32(v.w, h3, l3);
        dh[0] = __uint_as_float(h0); dh[1] = __uint_as_float(h1);
        dh[2] = __uint_as_float(h2); dh[3] = __uint_as_float(h3);
        dl[0] = __uint_as_float(l0); dl[1] = __uint_as_float(l1);
        dl[2] = __uint_as_float(l2); dl[3] = __uint_as_float(l3);
    }
    __syncthreads();

    const int warp = tid >> 5;
    const int lane = tid & 31;
    const int g = lane >> 2;
    const int t = lane & 3;

    const int row0 = (blockIdx.x >> 1) * 256 + warp * 32;
    const float* aT = AT + row0 + g;   // lane base; +16s, +8 row offsets; k*NP strides

    float acc[2][8][4];
#pragma unroll
    for (int s = 0; s < 2; s++)
#pragma unroll
        for (int j = 0; j < 8; j++)
#pragma unroll
            for (int q = 0; q < 4; q++) acc[s][j][q] = 0.f;

#pragma unroll
    for (int kk = 0; kk < 128; kk += 8) {
        uint32_t ah[2][4], al[2][4];
        const float* pk0 = aT + (size_t)(kk + t) * NP;
        const float* pk1 = aT + (size_t)(kk + t + 4) * NP;
#pragma unroll
        for (int s = 0; s < 2; s++) {
            float f0 = __ldg(pk0 + 16 * s);      // row rA = row0+g+16s,  k = kk+t
            float f1 = __ldg(pk0 + 16 * s + 8);  // row rB = rA+8,        k = kk+t
            float f2 = __ldg(pk1 + 16 * s);      // row rA,               k = kk+t+4
            float f3 = __ldg(pk1 + 16 * s + 8);  // row rB,               k = kk+t+4
            split_tf32(f0, ah[s][0], al[s][0]);
            split_tf32(f1, ah[s][1], al[s][1]);
            split_tf32(f2, ah[s][2], al[s][2]);
            split_tf32(f3, ah[s][3], al[s][3]);
        }

        const float* bh0 = &BsH[(kk + t) * BS_STRIDE + g];
        const float* bh1 = &BsH[(kk + t + 4) * BS_STRIDE + g];
        const float* bl0 = &BsL[(kk + t) * BS_STRIDE + g];
        const float* bl1 = &BsL[(kk + t + 4) * BS_STRIDE + g];

#pragma unroll
        for (int j = 0; j < 8; j++) {
            uint32_t b0h = __float_as_uint(bh0[j * 8]);
            uint32_t b1h = __float_as_uint(bh1[j * 8]);
            uint32_t b0l = __float_as_uint(bl0[j * 8]);
            uint32_t b1l = __float_as_uint(bl1[j * 8]);
#pragma unroll
            for (int s = 0; s < 2; s++) {
                mma_tf32(acc[s][j], al[s][0], al[s][1], al[s][2], al[s][3], b0h, b1h);
                mma_tf32(acc[s][j], ah[s][0], ah[s][1], ah[s][2], ah[s][3], b0l, b1l);
                mma_tf32(acc[s][j], ah[s][0], ah[s][1], ah[s][2], ah[s][3], b0h, b1h);
            }
        }
    }

    // epilogue (C row-major)
#pragma unroll
    for (int s = 0; s < 2; s++) {
        int rA = row0 + g + 16 * s;
        int rB = rA + 8;
        bool okA = rA < N;
        bool okB = rB < N;
#pragma unroll
        for (int j = 0; j < 8; j++) {
            float v0 = acc[s][j][0], v1 = acc[s][j][1];
            float v2 = acc[s][j][2], v3 = acc[s][j][3];
            if (RELU) {
                v0 = fmaxf(v0, 0.f); v1 = fmaxf(v1, 0.f);
                v2 = fmaxf(v2, 0.f); v3 = fmaxf(v3, 0.f);
            }
            int c = col_off + j * 8 + 2 * t;
            if (okA) *(float2*)(C + (size_t)rA * D + c) = make_float2(v0, v1);
            if (okB) *(float2*)(C + (size_t)rB * D + c) = make_float2(v2, v3);
        }
    }
}

// ---------------------------------------------------------------------------
extern "C" void kernel_launch(void* const* d_in, const int* in_sizes, int n_in,
                              void* d_out, int out_size) {
    const int*   edge_row  = (const int*)d_in[0];
    const int*   edge_col  = (const int*)d_in[1];
    const float* edge_vals = (const float*)d_in[2];
    const float* x         = (const float*)d_in[3];
    const float* sp        = (const float*)d_in[4];
    const float* lw        = (const float*)d_in[5];
    float*       out       = (float*)d_out;

    const int E = in_sizes[0];
    const int N = in_sizes[3] / D;
    const int L = in_sizes[5] / P;
    const int NP = ((N + 255) / 256) * 256;   // padded row stride for axT

    void *p_axT, *p_hA, *p_hB, *p_ww;
    cudaGetSymbolAddress(&p_axT, g_axT);
    cudaGetSymbolAddress(&p_hA, g_hA);
    cudaGetSymbolAddress(&p_hB, g_hB);
    cudaGetSymbolAddress(&p_ww, g_wwT);

    const int smem_bytes = 2 * 128 * BS_STRIDE * 4;   // 73728
    cudaFuncSetAttribute(gemm_tc<true>,  cudaFuncAttributeMaxDynamicSharedMemorySize, smem_bytes);
    cudaFuncSetAttribute(gemm_tc<false>, cudaFuncAttributeMaxDynamicSharedMemorySize, smem_bytes);

    build_row_ptr_k<<<(N + 256) / 256, 256>>>(edge_row, E, N);
    build_weights_k<<<L * D, D>>>(sp, lw);

    float* bufs[2] = {(float*)p_hA, (float*)p_hB};
    const float* hin = x;
    const int gemm_blocks = 2 * ((N + 255) / 256);
    const int spmm_blocks = (N + 7) / 8;

    for (int l = 0; l < L; l++) {
        spmm_t_k<<<spmm_blocks, 256>>>(edge_col, edge_vals, hin, N, NP);
        const float* Bm = (const float*)p_ww + (size_t)l * D * D;
        float* Cout = (l == L - 1) ? out : bufs[l & 1];
        if (l < L - 1)
            gemm_tc<true><<<gemm_blocks, 256, smem_bytes>>>((const float*)p_axT, Bm, Cout, N, NP);
        else
            gemm_tc<false><<<gemm_blocks, 256, smem_bytes>>>((const float*)p_axT, Bm, Cout, N, NP);
        hin = Cout;
    }
}

// round 8
// speedup vs baseline: 1.1242x; 1.1242x over previous
#include <cuda_runtime.h>
#include <cstdint>

#define D 128
#define P 8
#define NMAX 100000
#define LMAX 3
#define BS_STRIDE 72    // Bs stride: frag bank = (8t + 8j + g) % 32, all distinct

// Scratch (device globals — no allocation allowed)
__device__ float g_ax[(size_t)NMAX * D];
__device__ float g_hA[(size_t)NMAX * D];
__device__ float g_hB[(size_t)NMAX * D];
__device__ int   g_row_ptr[NMAX + 1];
__device__ float g_wwT[LMAX * D * D];   // [l][k][o]

// ---------------------------------------------------------------------------
__global__ void build_row_ptr_k(const int* __restrict__ edge_row, int E, int N) {
    int r = blockIdx.x * blockDim.x + threadIdx.x;
    if (r > N) return;
    int lo = 0, hi = E;
    while (lo < hi) {
        int mid = (lo + hi) >> 1;
        if (edge_row[mid] < r) lo = mid + 1; else hi = mid;
    }
    g_row_ptr[r] = lo;
}

// ---------------------------------------------------------------------------
__global__ void build_weights_k(const float* __restrict__ sp, const float* __restrict__ lw) {
    int l = blockIdx.x >> 7;
    int i = blockIdx.x & 127;
    int o = threadIdx.x;

    float w[P];
    float m = -1e30f;
#pragma unroll
    for (int p = 0; p < P; p++) { w[p] = lw[l * P + p]; m = fmaxf(m, w[p]); }
    float s = 0.f;
#pragma unroll
    for (int p = 0; p < P; p++) { w[p] = expf(w[p] - m); s += w[p]; }
    float inv = 1.f / s;

    const float* base = sp + (((size_t)l * D + o) * D + i) * P;
    float acc = 0.f;
#pragma unroll
    for (int p = 0; p < P; p++) acc = fmaf(base[p], w[p] * inv, acc);
    g_wwT[((size_t)l * D + i) * D + o] = acc;
}

// ---------------------------------------------------------------------------
// SpMM: one warp per row, 2-edge unroll, row-major output. (L2-gather floor.)
// ---------------------------------------------------------------------------
__global__ void spmm_k(const int* __restrict__ col, const float* __restrict__ val,
                       const float* __restrict__ h, int N) {
    int warp = (int)((blockIdx.x * blockDim.x + threadIdx.x) >> 5);
    int lane = threadIdx.x & 31;
    if (warp >= N) return;
    int s = g_row_ptr[warp];
    int e = g_row_ptr[warp + 1];
    float4 acc0 = make_float4(0.f, 0.f, 0.f, 0.f);
    float4 acc1 = make_float4(0.f, 0.f, 0.f, 0.f);
    int k = s;
    for (; k + 1 < e; k += 2) {
        int   c0 = __ldg(col + k);
        int   c1 = __ldg(col + k + 1);
        float v0 = __ldg(val + k);
        float v1 = __ldg(val + k + 1);
        float4 h0 = __ldg(((const float4*)(h + (size_t)c0 * D)) + lane);
        float4 h1 = __ldg(((const float4*)(h + (size_t)c1 * D)) + lane);
        acc0.x = fmaf(v0, h0.x, acc0.x); acc0.y = fmaf(v0, h0.y, acc0.y);
        acc0.z = fmaf(v0, h0.z, acc0.z); acc0.w = fmaf(v0, h0.w, acc0.w);
        acc1.x = fmaf(v1, h1.x, acc1.x); acc1.y = fmaf(v1, h1.y, acc1.y);
        acc1.z = fmaf(v1, h1.z, acc1.z); acc1.w = fmaf(v1, h1.w, acc1.w);
    }
    if (k < e) {
        int   c0 = __ldg(col + k);
        float v0 = __ldg(val + k);
        float4 h0 = __ldg(((const float4*)(h + (size_t)c0 * D)) + lane);
        acc0.x = fmaf(v0, h0.x, acc0.x); acc0.y = fmaf(v0, h0.y, acc0.y);
        acc0.z = fmaf(v0, h0.z, acc0.z); acc0.w = fmaf(v0, h0.w, acc0.w);
    }
    acc0.x += acc1.x; acc0.y += acc1.y; acc0.z += acc1.z; acc0.w += acc1.w;
    ((float4*)(g_ax + (size_t)warp * D))[lane] = acc0;
}

// ---------------------------------------------------------------------------
__device__ __forceinline__ void mma_tf32(float (&d)[4],
                                         uint32_t a0, uint32_t a1, uint32_t a2, uint32_t a3,
                                         uint32_t b0, uint32_t b1) {
    asm volatile(
        "mma.sync.aligned.m16n8k8.row.col.f32.tf32.tf32.f32 "
        "{%0,%1,%2,%3},{%4,%5,%6,%7},{%8,%9},{%0,%1,%2,%3};"
        : "+f"(d[0]), "+f"(d[1]), "+f"(d[2]), "+f"(d[3])
        : "r"(a0), "r"(a1), "r"(a2), "r"(a3), "r"(b0), "r"(b1));
}

__device__ __forceinline__ void split_tf32(float v, uint32_t& hi, uint32_t& lo) {
    uint32_t h = __float_as_uint(v) & 0xffffe000u;
    hi = h;
    lo = __float_as_uint(v - __uint_as_float(h));
}

// ---------------------------------------------------------------------------
// Tensor-core GEMM (3xTF32): block = 256 rows x 64 cols, warp = 32 rows x 64.
// k-PERMUTED fragments: within each 16-k group, physical k = 16kb + 4t + 2c + hi
// maps to (chunk c, frag t + 4*hi). A loads become one float4 per row per 16k
// (full 32B sectors, 4x fewer L1 wavefronts). B staged k-permuted + hi/lo
// pre-split, so inner loop is pure LDS + HMMA. 2 blocks/SM.
// ---------------------------------------------------------------------------
template <bool RELU>
__global__ __launch_bounds__(256, 2) void gemm_tc(const float* __restrict__ A,
                                                  const float* __restrict__ B,
                                                  float* __restrict__ C, int N) {
    extern __shared__ float smem[];
    float* BsH = smem;                    // [128][BS_STRIDE] (k-permuted rows)
    float* BsL = smem + 128 * BS_STRIDE;

    const int tid     = threadIdx.x;
    const int col_off = (blockIdx.x & 1) << 6;   // 0 or 64

    // stage B slice (128 x 64): permute k-rows, split hi/lo
#pragma unroll
    for (int i = tid; i < 128 * 16; i += 256) {
        int p   = i >> 4;            // physical k row
        int c4  = (i & 15) << 2;
        int pk  = p & 15;
        // logical row within 16-group: f + 8c, where t=pk>>2, hi=pk&1, c=(pk>>1)&1
        int lpk = (pk >> 2) + ((pk & 1) << 2) + ((pk & 2) << 2);
        int lrow = (p & ~15) | lpk;
        float4 v = __ldg((const float4*)(B + p * 128 + col_off + c4));
        float* dh = &BsH[lrow * BS_STRIDE + c4];
        float* dl = &BsL[lrow * BS_STRIDE + c4];
        uint32_t h0, l0, h1, l1, h2, l2, h3, l3;
        split_tf32(v.x, h0, l0); split_tf32(v.y, h1, l1);
        split_tf32(v.z, h2, l2); split_tf32(v.w, h3, l3);
        dh[0] = __uint_as_float(h0); dh[1] = __uint_as_float(h1);
        dh[2] = __uint_as_float(h2); dh[3] = __uint_as_float(h3);
        dl[0] = __uint_as_float(l0); dl[1] = __uint_as_float(l1);
        dl[2] = __uint_as_float(l2); dl[3] = __uint_as_float(l3);
    }
    __syncthreads();

    const int warp = tid >> 5;
    const int lane = tid & 31;
    const int g = lane >> 2;
    const int t = lane & 3;

    const int row0 = (blockIdx.x >> 1) * 256 + warp * 32;

    int  r[4] = {row0 + g, row0 + g + 8, row0 + g + 16, row0 + g + 24};
    bool ok[4];
    const float* pA[4];
#pragma unroll
    for (int q = 0; q < 4; q++) {
        ok[q] = r[q] < N;
        pA[q] = A + (size_t)r[q] * D + 4 * t;
    }

    float acc[2][8][4];
#pragma unroll
    for (int s = 0; s < 2; s++)
#pragma unroll
        for (int j = 0; j < 8; j++)
#pragma unroll
            for (int q = 0; q < 4; q++) acc[s][j][q] = 0.f;

#pragma unroll
    for (int kb = 0; kb < 8; kb++) {
        // one float4 per row: phys k = 16kb + 4t .. 4t+3
        float4 v[4];
#pragma unroll
        for (int q = 0; q < 4; q++)
            v[q] = ok[q] ? __ldg((const float4*)(pA[q] + kb * 16))
                         : make_float4(0.f, 0.f, 0.f, 0.f);

#pragma unroll
        for (int c = 0; c < 2; c++) {
            // fragment floats: chunk c uses (x,y) for c=0, (z,w) for c=1
            uint32_t ah[2][4], al[2][4];
#pragma unroll
            for (int s = 0; s < 2; s++) {
                float f0 = (c == 0) ? v[2*s].x   : v[2*s].z;    // rA, frag t
                float f2 = (c == 0) ? v[2*s].y   : v[2*s].w;    // rA, frag t+4
                float f1 = (c == 0) ? v[2*s+1].x : v[2*s+1].z;  // rB, frag t
                float f3 = (c == 0) ? v[2*s+1].y : v[2*s+1].w;  // rB, frag t+4
                split_tf32(f0, ah[s][0], al[s][0]);
                split_tf32(f1, ah[s][1], al[s][1]);
                split_tf32(f2, ah[s][2], al[s][2]);
                split_tf32(f3, ah[s][3], al[s][3]);
            }

            const int kk = kb * 16 + c * 8;   // logical chunk base
            const float* bh0 = &BsH[(kk + t) * BS_STRIDE + g];
            const float* bh1 = &BsH[(kk + t + 4) * BS_STRIDE + g];
            const float* bl0 = &BsL[(kk + t) * BS_STRIDE + g];
            const float* bl1 = &BsL[(kk + t + 4) * BS_STRIDE + g];

#pragma unroll
            for (int j = 0; j < 8; j++) {
                uint32_t b0h = __float_as_uint(bh0[j * 8]);
                uint32_t b1h = __float_as_uint(bh1[j * 8]);
                uint32_t b0l = __float_as_uint(bl0[j * 8]);
                uint32_t b1l = __float_as_uint(bl1[j * 8]);
#pragma unroll
                for (int s = 0; s < 2; s++) {
                    mma_tf32(acc[s][j], al[s][0], al[s][1], al[s][2], al[s][3], b0h, b1h);
                    mma_tf32(acc[s][j], ah[s][0], ah[s][1], ah[s][2], ah[s][3], b0l, b1l);
                    mma_tf32(acc[s][j], ah[s][0], ah[s][1], ah[s][2], ah[s][3], b0h, b1h);
                }
            }
        }
    }

    // epilogue
#pragma unroll
    for (int s = 0; s < 2; s++) {
#pragma unroll
        for (int j = 0; j < 8; j++) {
            float v0 = acc[s][j][0], v1 = acc[s][j][1];
            float v2 = acc[s][j][2], v3 = acc[s][j][3];
            if (RELU) {
                v0 = fmaxf(v0, 0.f); v1 = fmaxf(v1, 0.f);
                v2 = fmaxf(v2, 0.f); v3 = fmaxf(v3, 0.f);
            }
            int c = col_off + j * 8 + 2 * t;
            if (ok[2*s])   *(float2*)(C + (size_t)r[2*s]   * D + c) = make_float2(v0, v1);
            if (ok[2*s+1]) *(float2*)(C + (size_t)r[2*s+1] * D + c) = make_float2(v2, v3);
        }
    }
}

// ---------------------------------------------------------------------------
extern "C" void kernel_launch(void* const* d_in, const int* in_sizes, int n_in,
                              void* d_out, int out_size) {
    const int*   edge_row  = (const int*)d_in[0];
    const int*   edge_col  = (const int*)d_in[1];
    const float* edge_vals = (const float*)d_in[2];
    const float* x         = (const float*)d_in[3];
    const float* sp        = (const float*)d_in[4];
    const float* lw        = (const float*)d_in[5];
    float*       out       = (float*)d_out;

    const int E = in_sizes[0];
    const int N = in_sizes[3] / D;
    const int L = in_sizes[5] / P;

    void *p_ax, *p_hA, *p_hB, *p_ww;
    cudaGetSymbolAddress(&p_ax, g_ax);
    cudaGetSymbolAddress(&p_hA, g_hA);
    cudaGetSymbolAddress(&p_hB, g_hB);
    cudaGetSymbolAddress(&p_ww, g_wwT);

    const int smem_bytes = 2 * 128 * BS_STRIDE * 4;   // 73728
    cudaFuncSetAttribute(gemm_tc<true>,  cudaFuncAttributeMaxDynamicSharedMemorySize, smem_bytes);
    cudaFuncSetAttribute(gemm_tc<false>, cudaFuncAttributeMaxDynamicSharedMemorySize, smem_bytes);

    build_row_ptr_k<<<(N + 256) / 256, 256>>>(edge_row, E, N);
    build_weights_k<<<L * D, D>>>(sp, lw);

    float* bufs[2] = {(float*)p_hA, (float*)p_hB};
    const float* hin = x;
    const int gemm_blocks = 2 * ((N + 255) / 256);
    const int spmm_blocks = (N + 7) / 8;

    for (int l = 0; l < L; l++) {
        spmm_k<<<spmm_blocks, 256>>>(edge_col, edge_vals, hin, N);
        const float* Bm = (const float*)p_ww + (size_t)l * D * D;
        float* Cout = (l == L - 1) ? out : bufs[l & 1];
        if (l < L - 1)
            gemm_tc<true><<<gemm_blocks, 256, smem_bytes>>>((const float*)p_ax, Bm, Cout, N);
        else
            gemm_tc<false><<<gemm_blocks, 256, smem_bytes>>>((const float*)p_ax, Bm, Cout, N);
        hin = Cout;
    }
}

// round 9
// speedup vs baseline: 1.4205x; 1.2635x over previous
#include <cuda_runtime.h>
#include <cstdint>

#define D 128
#define P 8
#define NMAX 100000
#define LMAX 3
#define BS2 130   // Bs stride (words): ≡2 mod 8 -> float2 frag loads conflict-free

// Scratch (device globals — no allocation allowed)
__device__ float g_ax[(size_t)NMAX * D];
__device__ float g_hA[(size_t)NMAX * D];
__device__ float g_hB[(size_t)NMAX * D];
__device__ int   g_row_ptr[NMAX + 1];
__device__ float g_wwT[LMAX * D * D];   // [l][k][o]

// ---------------------------------------------------------------------------
__global__ void build_row_ptr_k(const int* __restrict__ edge_row, int E, int N) {
    int r = blockIdx.x * blockDim.x + threadIdx.x;
    if (r > N) return;
    int lo = 0, hi = E;
    while (lo < hi) {
        int mid = (lo + hi) >> 1;
        if (edge_row[mid] < r) lo = mid + 1; else hi = mid;
    }
    g_row_ptr[r] = lo;
}

// ---------------------------------------------------------------------------
__global__ void build_weights_k(const float* __restrict__ sp, const float* __restrict__ lw) {
    int l = blockIdx.x >> 7;
    int i = blockIdx.x & 127;
    int o = threadIdx.x;

    float w[P];
    float m = -1e30f;
#pragma unroll
    for (int p = 0; p < P; p++) { w[p] = lw[l * P + p]; m = fmaxf(m, w[p]); }
    float s = 0.f;
#pragma unroll
    for (int p = 0; p < P; p++) { w[p] = expf(w[p] - m); s += w[p]; }
    float inv = 1.f / s;

    const float* base = sp + (((size_t)l * D + o) * D + i) * P;
    float acc = 0.f;
#pragma unroll
    for (int p = 0; p < P; p++) acc = fmaf(base[p], w[p] * inv, acc);
    g_wwT[((size_t)l * D + i) * D + o] = acc;
}

// ---------------------------------------------------------------------------
// SpMM: one warp per row, 2-edge unroll, row-major output. (L2-gather floor.)
// ---------------------------------------------------------------------------
__global__ void spmm_k(const int* __restrict__ col, const float* __restrict__ val,
                       const float* __restrict__ h, int N) {
    int warp = (int)((blockIdx.x * blockDim.x + threadIdx.x) >> 5);
    int lane = threadIdx.x & 31;
    if (warp >= N) return;
    int s = g_row_ptr[warp];
    int e = g_row_ptr[warp + 1];
    float4 acc0 = make_float4(0.f, 0.f, 0.f, 0.f);
    float4 acc1 = make_float4(0.f, 0.f, 0.f, 0.f);
    int k = s;
    for (; k + 1 < e; k += 2) {
        int   c0 = __ldg(col + k);
        int   c1 = __ldg(col + k + 1);
        float v0 = __ldg(val + k);
        float v1 = __ldg(val + k + 1);
        float4 h0 = __ldg(((const float4*)(h + (size_t)c0 * D)) + lane);
        float4 h1 = __ldg(((const float4*)(h + (size_t)c1 * D)) + lane);
        acc0.x = fmaf(v0, h0.x, acc0.x); acc0.y = fmaf(v0, h0.y, acc0.y);
        acc0.z = fmaf(v0, h0.z, acc0.z); acc0.w = fmaf(v0, h0.w, acc0.w);
        acc1.x = fmaf(v1, h1.x, acc1.x); acc1.y = fmaf(v1, h1.y, acc1.y);
        acc1.z = fmaf(v1, h1.z, acc1.z); acc1.w = fmaf(v1, h1.w, acc1.w);
    }
    if (k < e) {
        int   c0 = __ldg(col + k);
        float v0 = __ldg(val + k);
        float4 h0 = __ldg(((const float4*)(h + (size_t)c0 * D)) + lane);
        acc0.x = fmaf(v0, h0.x, acc0.x); acc0.y = fmaf(v0, h0.y, acc0.y);
        acc0.z = fmaf(v0, h0.z, acc0.z); acc0.w = fmaf(v0, h0.w, acc0.w);
    }
    acc0.x += acc1.x; acc0.y += acc1.y; acc0.z += acc1.z; acc0.w += acc1.w;
    ((float4*)(g_ax + (size_t)warp * D))[lane] = acc0;
}

// ---------------------------------------------------------------------------
__device__ __forceinline__ void mma_tf32(float (&d)[4],
                                         uint32_t a0, uint32_t a1, uint32_t a2, uint32_t a3,
                                         uint32_t b0, uint32_t b1) {
    asm volatile(
        "mma.sync.aligned.m16n8k8.row.col.f32.tf32.tf32.f32 "
        "{%0,%1,%2,%3},{%4,%5,%6,%7},{%8,%9},{%0,%1,%2,%3};"
        : "+f"(d[0]), "+f"(d[1]), "+f"(d[2]), "+f"(d[3])
        : "r"(a0), "r"(a1), "r"(a2), "r"(a3), "r"(b0), "r"(b1));
}

__device__ __forceinline__ uint32_t cvt_tf32(float x) {
    uint32_t r;
    asm("cvt.rn.tf32.f32 %0, %1;" : "=r"(r) : "f"(x));
    return r;
}

// ---------------------------------------------------------------------------
// Tensor-core GEMM (1xTF32, RN-rounded): block = 128 rows x 128 cols,
// warp = 32 rows x 64 cols. k-permuted A loads (one LDG.128 per row per 16k).
// B staged tf32-converted, k-permuted, j-contiguous (Bs[k][g*8+j]) so frag
// loads are conflict-free float2. 2 blocks/SM.
// ---------------------------------------------------------------------------
template <bool RELU>
__global__ __launch_bounds__(256, 2) void gemm_tc(const float* __restrict__ A,
                                                  const float* __restrict__ B,
                                                  float* __restrict__ C, int N) {
    extern __shared__ float Bs[];   // [128][BS2], logical rows k-permuted

    const int tid = threadIdx.x;

    // stage B (128 x 128): permute k-rows, swap (j,g) within 64-halves, cvt tf32
#pragma unroll
    for (int i = tid; i < 128 * 32; i += 256) {
        int p  = i >> 5;             // physical k row
        int c4 = (i & 31) << 2;      // col base
        int pk = p & 15;
        int lpk = (pk >> 2) + ((pk & 1) << 2) + ((pk & 2) << 2);
        int lrow = (p & ~15) | lpk;
        float4 v = __ldg((const float4*)(B + p * 128 + c4));
        float vv[4] = {v.x, v.y, v.z, v.w};
#pragma unroll
        for (int e = 0; e < 4; e++) {
            int o = c4 + e;
            int hh = o >> 6;
            int j  = (o >> 3) & 7;
            int g  = o & 7;
            Bs[lrow * BS2 + (hh << 6) + (g << 3) + j] =
                __uint_as_float(cvt_tf32(vv[e]));
        }
    }
    __syncthreads();

    const int warp = tid >> 5;
    const int lane = tid & 31;
    const int g  = lane >> 2;
    const int t  = lane & 3;
    const int wr = warp >> 1;     // 0..3 row group of 32
    const int wc = warp & 1;      // 0..1 col group of 64

    const int row0 = blockIdx.x * 128 + wr * 32;

    int  r[4] = {row0 + g, row0 + g + 8, row0 + g + 16, row0 + g + 24};
    bool ok[4];
    const float* pA[4];
#pragma unroll
    for (int q = 0; q < 4; q++) {
        ok[q] = r[q] < N;
        pA[q] = A + (size_t)r[q] * D + 4 * t;
    }

    float acc[2][8][4];
#pragma unroll
    for (int s = 0; s < 2; s++)
#pragma unroll
        for (int j = 0; j < 8; j++)
#pragma unroll
            for (int q = 0; q < 4; q++) acc[s][j][q] = 0.f;

    const int bbase = wc * 64 + g * 8;

#pragma unroll
    for (int kb = 0; kb < 8; kb++) {
        // one float4 per row: phys k = 16kb + 4t .. 4t+3
        float4 v[4];
#pragma unroll
        for (int q = 0; q < 4; q++)
            v[q] = ok[q] ? __ldg((const float4*)(pA[q] + kb * 16))
                         : make_float4(0.f, 0.f, 0.f, 0.f);

#pragma unroll
        for (int c = 0; c < 2; c++) {
            // chunk c: slot t <- comp[2c], slot t+4 <- comp[2c+1]
            uint32_t a0[2], a1[2], a2[2], a3[2];
#pragma unroll
            for (int s = 0; s < 2; s++) {
                float f0 = (c == 0) ? v[2*s].x   : v[2*s].z;
                float f2 = (c == 0) ? v[2*s].y   : v[2*s].w;
                float f1 = (c == 0) ? v[2*s+1].x : v[2*s+1].z;
                float f3 = (c == 0) ? v[2*s+1].y : v[2*s+1].w;
                a0[s] = cvt_tf32(f0);
                a1[s] = cvt_tf32(f1);
                a2[s] = cvt_tf32(f2);
                a3[s] = cvt_tf32(f3);
            }

            const int kk = kb * 16 + c * 8;   // logical chunk base
            const float* brow0 = &Bs[(kk + t) * BS2 + bbase];
            const float* brow1 = &Bs[(kk + t + 4) * BS2 + bbase];
            uint2 b0p[4], b1p[4];
#pragma unroll
            for (int m = 0; m < 4; m++) {
                b0p[m] = *(const uint2*)(brow0 + 2 * m);
                b1p[m] = *(const uint2*)(brow1 + 2 * m);
            }

#pragma unroll
            for (int j = 0; j < 8; j++) {
                uint32_t b0 = (j & 1) ? b0p[j >> 1].y : b0p[j >> 1].x;
                uint32_t b1 = (j & 1) ? b1p[j >> 1].y : b1p[j >> 1].x;
#pragma unroll
                for (int s = 0; s < 2; s++)
                    mma_tf32(acc[s][j], a0[s], a1[s], a2[s], a3[s], b0, b1);
            }
        }
    }

    // epilogue
#pragma unroll
    for (int s = 0; s < 2; s++) {
        int rA = row0 + g + 16 * s;
        int rB = rA + 8;
        bool okA = rA < N;
        bool okB = rB < N;
#pragma unroll
        for (int j = 0; j < 8; j++) {
            float v0 = acc[s][j][0], v1 = acc[s][j][1];
            float v2 = acc[s][j][2], v3 = acc[s][j][3];
            if (RELU) {
                v0 = fmaxf(v0, 0.f); v1 = fmaxf(v1, 0.f);
                v2 = fmaxf(v2, 0.f); v3 = fmaxf(v3, 0.f);
            }
            int c = wc * 64 + j * 8 + 2 * t;
            if (okA) *(float2*)(C + (size_t)rA * D + c) = make_float2(v0, v1);
            if (okB) *(float2*)(C + (size_t)rB * D + c) = make_float2(v2, v3);
        }
    }
}

// ---------------------------------------------------------------------------
extern "C" void kernel_launch(void* const* d_in, const int* in_sizes, int n_in,
                              void* d_out, int out_size) {
    const int*   edge_row  = (const int*)d_in[0];
    const int*   edge_col  = (const int*)d_in[1];
    const float* edge_vals = (const float*)d_in[2];
    const float* x         = (const float*)d_in[3];
    const float* sp        = (const float*)d_in[4];
    const float* lw        = (const float*)d_in[5];
    float*       out       = (float*)d_out;

    const int E = in_sizes[0];
    const int N = in_sizes[3] / D;
    const int L = in_sizes[5] / P;

    void *p_ax, *p_hA, *p_hB, *p_ww;
    cudaGetSymbolAddress(&p_ax, g_ax);
    cudaGetSymbolAddress(&p_hA, g_hA);
    cudaGetSymbolAddress(&p_hB, g_hB);
    cudaGetSymbolAddress(&p_ww, g_wwT);

    const int smem_bytes = 128 * BS2 * 4;   // 66560
    cudaFuncSetAttribute(gemm_tc<true>,  cudaFuncAttributeMaxDynamicSharedMemorySize, smem_bytes);
    cudaFuncSetAttribute(gemm_tc<false>, cudaFuncAttributeMaxDynamicSharedMemorySize, smem_bytes);

    build_row_ptr_k<<<(N + 256) / 256, 256>>>(edge_row, E, N);
    build_weights_k<<<L * D, D>>>(sp, lw);

    float* bufs[2] = {(float*)p_hA, (float*)p_hB};
    const float* hin = x;
    const int gemm_blocks = (N + 127) / 128;
    const int spmm_blocks = (N + 7) / 8;

    for (int l = 0; l < L; l++) {
        spmm_k<<<spmm_blocks, 256>>>(edge_col, edge_vals, hin, N);
        const float* Bm = (const float*)p_ww + (size_t)l * D * D;
        float* Cout = (l == L - 1) ? out : bufs[l & 1];
        if (l < L - 1)
            gemm_tc<true><<<gemm_blocks, 256, smem_bytes>>>((const float*)p_ax, Bm, Cout, N);
        else
            gemm_tc<false><<<gemm_blocks, 256, smem_bytes>>>((const float*)p_ax, Bm, Cout, N);
        hin = Cout;
    }
}

// round 10
// speedup vs baseline: 1.5380x; 1.0827x over previous
#include <cuda_runtime.h>
#include <cuda_bf16.h>
#include <cstdint>

#define D 128
#define P 8
#define NMAX 100000
#define LMAX 3
#define BS2 130   // Bs stride (words): ≡2 mod 8 -> float2 frag loads conflict-free

// Scratch (device globals — no allocation allowed)
__device__ float          g_ax[(size_t)NMAX * D];          // SpMM out (fp32)
__device__ __nv_bfloat16  g_xbf[(size_t)NMAX * D];         // x converted to bf16
__device__ __nv_bfloat16  g_hA[(size_t)NMAX * D];          // ping (bf16)
__device__ __nv_bfloat16  g_hB[(size_t)NMAX * D];          // pong (bf16)
__device__ int            g_row_ptr[NMAX + 1];
__device__ float          g_wwT[LMAX * D * D];             // [l][k][o]

// ---------------------------------------------------------------------------
__global__ void build_row_ptr_k(const int* __restrict__ edge_row, int E, int N) {
    int r = blockIdx.x * blockDim.x + threadIdx.x;
    if (r > N) return;
    int lo = 0, hi = E;
    while (lo < hi) {
        int mid = (lo + hi) >> 1;
        if (edge_row[mid] < r) lo = mid + 1; else hi = mid;
    }
    g_row_ptr[r] = lo;
}

// ---------------------------------------------------------------------------
__global__ void build_weights_k(const float* __restrict__ sp, const float* __restrict__ lw) {
    int l = blockIdx.x >> 7;
    int i = blockIdx.x & 127;
    int o = threadIdx.x;

    float w[P];
    float m = -1e30f;
#pragma unroll
    for (int p = 0; p < P; p++) { w[p] = lw[l * P + p]; m = fmaxf(m, w[p]); }
    float s = 0.f;
#pragma unroll
    for (int p = 0; p < P; p++) { w[p] = expf(w[p] - m); s += w[p]; }
    float inv = 1.f / s;

    const float* base = sp + (((size_t)l * D + o) * D + i) * P;
    float acc = 0.f;
#pragma unroll
    for (int p = 0; p < P; p++) acc = fmaf(base[p], w[p] * inv, acc);
    g_wwT[((size_t)l * D + i) * D + o] = acc;
}

// ---------------------------------------------------------------------------
// Convert x (fp32) -> bf16, RN. One float4 (4 vals) per thread-iter.
// ---------------------------------------------------------------------------
__global__ void cvt_x_k(const float* __restrict__ x, int total4) {
    int i = blockIdx.x * blockDim.x + threadIdx.x;
    if (i >= total4) return;
    float4 v = __ldg(((const float4*)x) + i);
    __nv_bfloat162 a = __floats2bfloat162_rn(v.x, v.y);
    __nv_bfloat162 b = __floats2bfloat162_rn(v.z, v.w);
    ((__nv_bfloat162*)g_xbf)[2 * i]     = a;
    ((__nv_bfloat162*)g_xbf)[2 * i + 1] = b;
}

// ---------------------------------------------------------------------------
// SpMM over bf16 features: one warp per row, 2-edge unroll, fp32 accumulate,
// row-major fp32 output. Each lane owns 4 cols (uint2 = 4 bf16 per edge).
// ---------------------------------------------------------------------------
__global__ void spmm_k(const int* __restrict__ col, const float* __restrict__ val,
                       const __nv_bfloat16* __restrict__ h, int N) {
    int warp = (int)((blockIdx.x * blockDim.x + threadIdx.x) >> 5);
    int lane = threadIdx.x & 31;
    if (warp >= N) return;
    int s = g_row_ptr[warp];
    int e = g_row_ptr[warp + 1];
    float4 acc0 = make_float4(0.f, 0.f, 0.f, 0.f);
    float4 acc1 = make_float4(0.f, 0.f, 0.f, 0.f);
    int k = s;
    for (; k + 1 < e; k += 2) {
        int   c0 = __ldg(col + k);
        int   c1 = __ldg(col + k + 1);
        float v0 = __ldg(val + k);
        float v1 = __ldg(val + k + 1);
        uint2 u0 = __ldg((const uint2*)(h + (size_t)c0 * D) + lane);
        uint2 u1 = __ldg((const uint2*)(h + (size_t)c1 * D) + lane);
        float f00 = __uint_as_float(u0.x << 16);
        float f01 = __uint_as_float(u0.x & 0xffff0000u);
        float f02 = __uint_as_float(u0.y << 16);
        float f03 = __uint_as_float(u0.y & 0xffff0000u);
        float f10 = __uint_as_float(u1.x << 16);
        float f11 = __uint_as_float(u1.x & 0xffff0000u);
        float f12 = __uint_as_float(u1.y << 16);
        float f13 = __uint_as_float(u1.y & 0xffff0000u);
        acc0.x = fmaf(v0, f00, acc0.x); acc0.y = fmaf(v0, f01, acc0.y);
        acc0.z = fmaf(v0, f02, acc0.z); acc0.w = fmaf(v0, f03, acc0.w);
        acc1.x = fmaf(v1, f10, acc1.x); acc1.y = fmaf(v1, f11, acc1.y);
        acc1.z = fmaf(v1, f12, acc1.z); acc1.w = fmaf(v1, f13, acc1.w);
    }
    if (k < e) {
        int   c0 = __ldg(col + k);
        float v0 = __ldg(val + k);
        uint2 u0 = __ldg((const uint2*)(h + (size_t)c0 * D) + lane);
        float f00 = __uint_as_float(u0.x << 16);
        float f01 = __uint_as_float(u0.x & 0xffff0000u);
        float f02 = __uint_as_float(u0.y << 16);
        float f03 = __uint_as_float(u0.y & 0xffff0000u);
        acc0.x = fmaf(v0, f00, acc0.x); acc0.y = fmaf(v0, f01, acc0.y);
        acc0.z = fmaf(v0, f02, acc0.z); acc0.w = fmaf(v0, f03, acc0.w);
    }
    acc0.x += acc1.x; acc0.y += acc1.y; acc0.z += acc1.z; acc0.w += acc1.w;
    ((float4*)(g_ax + (size_t)warp * D))[lane] = acc0;
}

// ---------------------------------------------------------------------------
__device__ __forceinline__ void mma_tf32(float (&d)[4],
                                         uint32_t a0, uint32_t a1, uint32_t a2, uint32_t a3,
                                         uint32_t b0, uint32_t b1) {
    asm volatile(
        "mma.sync.aligned.m16n8k8.row.col.f32.tf32.tf32.f32 "
        "{%0,%1,%2,%3},{%4,%5,%6,%7},{%8,%9},{%0,%1,%2,%3};"
        : "+f"(d[0]), "+f"(d[1]), "+f"(d[2]), "+f"(d[3])
        : "r"(a0), "r"(a1), "r"(a2), "r"(a3), "r"(b0), "r"(b1));
}

__device__ __forceinline__ uint32_t cvt_tf32(float x) {
    uint32_t r;
    asm("cvt.rn.tf32.f32 %0, %1;" : "=r"(r) : "f"(x));
    return r;
}

// ---------------------------------------------------------------------------
// Tensor-core GEMM (1xTF32, RN): block = 128 rows x 128 cols, warp 32x64.
// k-permuted A LDG.128; B tf32 k-permuted j-contiguous in smem. 2 blocks/SM.
// RELU layers emit bf16 (packed x2); final layer emits fp32.
// ---------------------------------------------------------------------------
template <bool RELU>
__global__ __launch_bounds__(256, 2) void gemm_tc(const float* __restrict__ A,
                                                  const float* __restrict__ B,
                                                  void* __restrict__ Cv, int N) {
    extern __shared__ float Bs[];   // [128][BS2], logical rows k-permuted

    const int tid = threadIdx.x;

    // stage B (128 x 128): permute k-rows, swap (j,g) within 64-halves, cvt tf32
#pragma unroll
    for (int i = tid; i < 128 * 32; i += 256) {
        int p  = i >> 5;
        int c4 = (i & 31) << 2;
        int pk = p & 15;
        int lpk = (pk >> 2) + ((pk & 1) << 2) + ((pk & 2) << 2);
        int lrow = (p & ~15) | lpk;
        float4 v = __ldg((const float4*)(B + p * 128 + c4));
        float vv[4] = {v.x, v.y, v.z, v.w};
#pragma unroll
        for (int e = 0; e < 4; e++) {
            int o = c4 + e;
            int hh = o >> 6;
            int j  = (o >> 3) & 7;
            int g  = o & 7;
            Bs[lrow * BS2 + (hh << 6) + (g << 3) + j] =
                __uint_as_float(cvt_tf32(vv[e]));
        }
    }
    __syncthreads();

    const int warp = tid >> 5;
    const int lane = tid & 31;
    const int g  = lane >> 2;
    const int t  = lane & 3;
    const int wr = warp >> 1;
    const int wc = warp & 1;

    const int row0 = blockIdx.x * 128 + wr * 32;

    int  r[4] = {row0 + g, row0 + g + 8, row0 + g + 16, row0 + g + 24};
    bool ok[4];
    const float* pA[4];
#pragma unroll
    for (int q = 0; q < 4; q++) {
        ok[q] = r[q] < N;
        pA[q] = A + (size_t)r[q] * D + 4 * t;
    }

    float acc[2][8][4];
#pragma unroll
    for (int s = 0; s < 2; s++)
#pragma unroll
        for (int j = 0; j < 8; j++)
#pragma unroll
            for (int q = 0; q < 4; q++) acc[s][j][q] = 0.f;

    const int bbase = wc * 64 + g * 8;

#pragma unroll
    for (int kb = 0; kb < 8; kb++) {
        float4 v[4];
#pragma unroll
        for (int q = 0; q < 4; q++)
            v[q] = ok[q] ? __ldg((const float4*)(pA[q] + kb * 16))
                         : make_float4(0.f, 0.f, 0.f, 0.f);

#pragma unroll
        for (int c = 0; c < 2; c++) {
            uint32_t a0[2], a1[2], a2[2], a3[2];
#pragma unroll
            for (int s = 0; s < 2; s++) {
                float f0 = (c == 0) ? v[2*s].x   : v[2*s].z;
                float f2 = (c == 0) ? v[2*s].y   : v[2*s].w;
                float f1 = (c == 0) ? v[2*s+1].x : v[2*s+1].z;
                float f3 = (c == 0) ? v[2*s+1].y : v[2*s+1].w;
                a0[s] = cvt_tf32(f0);
                a1[s] = cvt_tf32(f1);
                a2[s] = cvt_tf32(f2);
                a3[s] = cvt_tf32(f3);
            }

            const int kk = kb * 16 + c * 8;
            const float* brow0 = &Bs[(kk + t) * BS2 + bbase];
            const float* brow1 = &Bs[(kk + t + 4) * BS2 + bbase];
            uint2 b0p[4], b1p[4];
#pragma unroll
            for (int m = 0; m < 4; m++) {
                b0p[m] = *(const uint2*)(brow0 + 2 * m);
                b1p[m] = *(const uint2*)(brow1 + 2 * m);
            }

#pragma unroll
            for (int j = 0; j < 8; j++) {
                uint32_t b0 = (j & 1) ? b0p[j >> 1].y : b0p[j >> 1].x;
                uint32_t b1 = (j & 1) ? b1p[j >> 1].y : b1p[j >> 1].x;
#pragma unroll
                for (int s = 0; s < 2; s++)
                    mma_tf32(acc[s][j], a0[s], a1[s], a2[s], a3[s], b0, b1);
            }
        }
    }

    // epilogue
#pragma unroll
    for (int s = 0; s < 2; s++) {
        int rA = row0 + g + 16 * s;
        int rB = rA + 8;
        bool okA = rA < N;
        bool okB = rB < N;
#pragma unroll
        for (int j = 0; j < 8; j++) {
            float v0 = acc[s][j][0], v1 = acc[s][j][1];
            float v2 = acc[s][j][2], v3 = acc[s][j][3];
            int c = wc * 64 + j * 8 + 2 * t;
            if (RELU) {
                v0 = fmaxf(v0, 0.f); v1 = fmaxf(v1, 0.f);
                v2 = fmaxf(v2, 0.f); v3 = fmaxf(v3, 0.f);
                __nv_bfloat16* C = (__nv_bfloat16*)Cv;
                __nv_bfloat162 pA2 = __floats2bfloat162_rn(v0, v1);
                __nv_bfloat162 pB2 = __floats2bfloat162_rn(v2, v3);
                if (okA) *(__nv_bfloat162*)(C + (size_t)rA * D + c) = pA2;
                if (okB) *(__nv_bfloat162*)(C + (size_t)rB * D + c) = pB2;
            } else {
                float* C = (float*)Cv;
                if (okA) *(float2*)(C + (size_t)rA * D + c) = make_float2(v0, v1);
                if (okB) *(float2*)(C + (size_t)rB * D + c) = make_float2(v2, v3);
            }
        }
    }
}

// ---------------------------------------------------------------------------
extern "C" void kernel_launch(void* const* d_in, const int* in_sizes, int n_in,
                              void* d_out, int out_size) {
    const int*   edge_row  = (const int*)d_in[0];
    const int*   edge_col  = (const int*)d_in[1];
    const float* edge_vals = (const float*)d_in[2];
    const float* x         = (const float*)d_in[3];
    const float* sp        = (const float*)d_in[4];
    const float* lw        = (const float*)d_in[5];

    const int E = in_sizes[0];
    const int N = in_sizes[3] / D;
    const int L = in_sizes[5] / P;

    void *p_ax, *p_xbf, *p_hA, *p_hB, *p_ww;
    cudaGetSymbolAddress(&p_ax, g_ax);
    cudaGetSymbolAddress(&p_xbf, g_xbf);
    cudaGetSymbolAddress(&p_hA, g_hA);
    cudaGetSymbolAddress(&p_hB, g_hB);
    cudaGetSymbolAddress(&p_ww, g_wwT);

    const int smem_bytes = 128 * BS2 * 4;   // 66560
    cudaFuncSetAttribute(gemm_tc<true>,  cudaFuncAttributeMaxDynamicSharedMemorySize, smem_bytes);
    cudaFuncSetAttribute(gemm_tc<false>, cudaFuncAttributeMaxDynamicSharedMemorySize, smem_bytes);

    build_row_ptr_k<<<(N + 256) / 256, 256>>>(edge_row, E, N);
    build_weights_k<<<L * D, D>>>(sp, lw);
    const int total4 = N * D / 4;
    cvt_x_k<<<(total4 + 255) / 256, 256>>>(x, total4);

    __nv_bfloat16* bufs[2] = {(__nv_bfloat16*)p_hA, (__nv_bfloat16*)p_hB};
    const __nv_bfloat16* hin = (const __nv_bfloat16*)p_xbf;
    const int gemm_blocks = (N + 127) / 128;
    const int spmm_blocks = (N + 7) / 8;

    for (int l = 0; l < L; l++) {
        spmm_k<<<spmm_blocks, 256>>>(edge_col, edge_vals, hin, N);
        const float* Bm = (const float*)p_ww + (size_t)l * D * D;
        if (l < L - 1) {
            gemm_tc<true><<<gemm_blocks, 256, smem_bytes>>>((const float*)p_ax, Bm,
                                                            (void*)bufs[l & 1], N);
            hin = bufs[l & 1];
        } else {
            gemm_tc<false><<<gemm_blocks, 256, smem_bytes>>>((const float*)p_ax, Bm,
                                                             d_out, N);
        }
    }
}